// round 2
// baseline (speedup 1.0000x reference)
#include <cuda_runtime.h>
#include <math.h>

// Problem constants
constexpr int B_  = 16;
constexpr int H_  = 1024;
constexpr int CO_ = 512;
constexpr int NV_ = 2048;
constexpr int NQ_ = 2048;

// -------- scratch (device globals; no runtime allocation allowed) --------
__device__ float g_WqQt[(size_t)B_ * CO_ * NQ_];  // 64 MiB
__device__ float g_WvV [(size_t)B_ * CO_ * NV_];  // 64 MiB
__device__ float g_Pv  [(size_t)B_ * CO_ * H_ ];  // 32 MiB
__device__ float g_Rv  [(size_t)B_ * CO_ * H_ ];  // 32 MiB
__device__ float g_Mv  [(size_t)B_ * CO_ * NV_];  // 64 MiB
__device__ float g_Pq  [(size_t)B_ * CO_ * H_ ];  // 32 MiB
__device__ float g_Rq  [(size_t)B_ * CO_ * H_ ];  // 32 MiB
__device__ float g_Mq  [(size_t)B_ * CO_ * NQ_];  // 64 MiB
__device__ float g_logv[(size_t)B_ * NV_];
__device__ float g_logq[(size_t)B_ * NQ_];
__device__ float g_part[(size_t)B_ * 16 * H_];

// ---------------------------------------------------------------------------
// Batched SGEMM: Cm[M,N] = A[M,K] * B, block tile 128x128, K-tile 8.
// A is always row-major [M,K] (K contiguous, leading dim lda).
// BT=false: B is [K,N] (N contiguous, ldb). BT=true: B is [N,K] (K contiguous).
// All of M(=512), N, K divide the tile sizes exactly; no bounds checks.
// grid = (N/128, M/128, batch)
// ---------------------------------------------------------------------------
template <bool BT>
__global__ __launch_bounds__(256, 2)
void sgemm128(const float* __restrict__ A,  int lda, size_t sA,
              const float* __restrict__ Bm, int ldb, size_t sB,
              float* __restrict__ Cm,       int ldc, size_t sC,
              int K)
{
    __shared__ float As[8][128];
    __shared__ float Bs[8][128];

    const int tid = threadIdx.x;
    const int bx = blockIdx.x, by = blockIdx.y, bz = blockIdx.z;

    A  += (size_t)bz * sA + (size_t)(by * 128) * lda;
    Bm += (size_t)bz * sB;
    Cm += (size_t)bz * sC + (size_t)(by * 128) * ldc + (size_t)bx * 128;

    // A (and BT=true B) staging: row = tid/2 in [0,128), k4 = (tid&1)*4
    const int arow = tid >> 1;
    const int ak4  = (tid & 1) * 4;
    // BT=false B staging: krow = tid/32, col4 = (tid%32)*4
    const int bkrow = tid >> 5;
    const int bcol4 = (tid & 31) * 4;

    const int tx = tid & 15;   // 16 col-threads
    const int ty = tid >> 4;   // 16 row-threads

    float acc[8][8];
#pragma unroll
    for (int i = 0; i < 8; ++i)
#pragma unroll
        for (int j = 0; j < 8; ++j) acc[i][j] = 0.f;

    for (int k0 = 0; k0 < K; k0 += 8) {
        // stage A tile (transposed into As[k][m])
        float4 av = *reinterpret_cast<const float4*>(A + (size_t)arow * lda + k0 + ak4);
        As[ak4 + 0][arow] = av.x;
        As[ak4 + 1][arow] = av.y;
        As[ak4 + 2][arow] = av.z;
        As[ak4 + 3][arow] = av.w;

        if (BT) {
            const float4 bv = *reinterpret_cast<const float4*>(
                Bm + (size_t)(bx * 128 + arow) * ldb + k0 + ak4);
            Bs[ak4 + 0][arow] = bv.x;
            Bs[ak4 + 1][arow] = bv.y;
            Bs[ak4 + 2][arow] = bv.z;
            Bs[ak4 + 3][arow] = bv.w;
        } else {
            const float4 bv = *reinterpret_cast<const float4*>(
                Bm + (size_t)(k0 + bkrow) * ldb + (size_t)bx * 128 + bcol4);
            *reinterpret_cast<float4*>(&Bs[bkrow][bcol4]) = bv;
        }
        __syncthreads();

#pragma unroll
        for (int kk = 0; kk < 8; ++kk) {
            const float4 a0 = *reinterpret_cast<const float4*>(&As[kk][ty * 4]);
            const float4 a1 = *reinterpret_cast<const float4*>(&As[kk][64 + ty * 4]);
            const float4 b0 = *reinterpret_cast<const float4*>(&Bs[kk][tx * 4]);
            const float4 b1 = *reinterpret_cast<const float4*>(&Bs[kk][64 + tx * 4]);
            const float a[8] = {a0.x, a0.y, a0.z, a0.w, a1.x, a1.y, a1.z, a1.w};
            const float b[8] = {b0.x, b0.y, b0.z, b0.w, b1.x, b1.y, b1.z, b1.w};
#pragma unroll
            for (int i = 0; i < 8; ++i)
#pragma unroll
                for (int j = 0; j < 8; ++j)
                    acc[i][j] = fmaf(a[i], b[j], acc[i][j]);
        }
        __syncthreads();
    }

#pragma unroll
    for (int i = 0; i < 8; ++i) {
        const int r = (i < 4) ? (ty * 4 + i) : (64 + ty * 4 + (i - 4));
        float4 c0 = make_float4(acc[i][0], acc[i][1], acc[i][2], acc[i][3]);
        float4 c1 = make_float4(acc[i][4], acc[i][5], acc[i][6], acc[i][7]);
        *reinterpret_cast<float4*>(Cm + (size_t)r * ldc + tx * 4)      = c0;
        *reinterpret_cast<float4*>(Cm + (size_t)r * ldc + 64 + tx * 4) = c1;
    }
}

// ---------------------------------------------------------------------------
// logits[b, n] = sum_c w[c] * tanh(X[b,c,n] + Y[b,c,n])
// grid = (Ncol/256, B), block = 256
// ---------------------------------------------------------------------------
__global__ void logits_kernel(const float* __restrict__ X,
                              const float* __restrict__ Y,
                              const float* __restrict__ w,
                              float* __restrict__ lg, int Ncol)
{
    __shared__ float ws[CO_];
    const int tid = threadIdx.x;
    for (int c = tid; c < CO_; c += blockDim.x) ws[c] = w[c];
    __syncthreads();

    const int b = blockIdx.y;
    const int n = blockIdx.x * blockDim.x + tid;
    size_t idx = ((size_t)b * CO_) * Ncol + n;
    float acc = 0.f;
#pragma unroll 4
    for (int c = 0; c < CO_; ++c) {
        acc += ws[c] * tanhf(X[idx] + Y[idx]);
        idx += Ncol;
    }
    lg[(size_t)b * Ncol + n] = acc;
}

// ---------------------------------------------------------------------------
// softmax over Ncol (=2048) per batch; grid = B, block = 256
// ---------------------------------------------------------------------------
__global__ void softmax_kernel(const float* __restrict__ lg,
                               float* __restrict__ outp, int Ncol)
{
    __shared__ float buf[2048];
    __shared__ float red[256];
    const int b = blockIdx.x;
    const int tid = threadIdx.x;
    const float* x = lg + (size_t)b * Ncol;

    float mx = -INFINITY;
    for (int i = tid; i < Ncol; i += 256) {
        float v = x[i];
        buf[i] = v;
        mx = fmaxf(mx, v);
    }
    red[tid] = mx;
    __syncthreads();
    for (int s = 128; s > 0; s >>= 1) {
        if (tid < s) red[tid] = fmaxf(red[tid], red[tid + s]);
        __syncthreads();
    }
    mx = red[0];
    __syncthreads();

    float sm = 0.f;
    for (int i = tid; i < Ncol; i += 256) {
        float e = expf(buf[i] - mx);
        buf[i] = e;
        sm += e;
    }
    red[tid] = sm;
    __syncthreads();
    for (int s = 128; s > 0; s >>= 1) {
        if (tid < s) red[tid] += red[tid + s];
        __syncthreads();
    }
    const float inv = 1.f / red[0];
    for (int i = tid; i < Ncol; i += 256)
        outp[(size_t)b * Ncol + i] = buf[i] * inv;
}

// ---------------------------------------------------------------------------
// v[b,h] = sum_v a[b,v] * V[b,h,v]; warp per h row. grid=(H/8, B), block=256
// ---------------------------------------------------------------------------
__global__ void av_V_kernel(const float* __restrict__ a,
                            const float* __restrict__ V,
                            float* __restrict__ outv)
{
    const int b = blockIdx.y;
    const int h = blockIdx.x * 8 + (threadIdx.x >> 5);
    const int lane = threadIdx.x & 31;
    const float* row = V + ((size_t)b * H_ + h) * NV_;
    const float* av = a + (size_t)b * NV_;
    float acc = 0.f;
    for (int i = lane; i < NV_; i += 32) acc += av[i] * row[i];
#pragma unroll
    for (int off = 16; off > 0; off >>= 1)
        acc += __shfl_down_sync(0xffffffffu, acc, off);
    if (lane == 0) outv[(size_t)b * H_ + h] = acc;
}

// ---------------------------------------------------------------------------
// q[b,h] = sum_q a[b,q] * Q[b,q,h]; deterministic 2-stage reduction
// stage1: grid=(16, B), block=1024 (h = tid), each block handles 128 q's
// ---------------------------------------------------------------------------
__global__ void aq_Q_partial(const float* __restrict__ a,
                             const float* __restrict__ Q,
                             float* __restrict__ part)
{
    const int b = blockIdx.y, j = blockIdx.x;
    const int h = threadIdx.x;
    const float* aq = a + (size_t)b * NQ_;
    float acc = 0.f;
    const int q0 = j * (NQ_ / 16);
    for (int q = q0; q < q0 + NQ_ / 16; ++q)
        acc += aq[q] * Q[((size_t)b * NQ_ + q) * H_ + h];
    part[((size_t)b * 16 + j) * H_ + h] = acc;
}

__global__ void aq_Q_reduce(const float* __restrict__ part,
                            float* __restrict__ outq)
{
    const int b = blockIdx.x;
    const int h = threadIdx.x;
    float acc = 0.f;
#pragma unroll
    for (int j = 0; j < 16; ++j)
        acc += part[((size_t)b * 16 + j) * H_ + h];
    outq[(size_t)b * H_ + h] = acc;
}

// ---------------------------------------------------------------------------
extern "C" void kernel_launch(void* const* d_in, const int* in_sizes, int n_in,
                              void* d_out, int out_size)
{
    const float* V    = (const float*)d_in[0];  // [B, H, NV]
    const float* Q    = (const float*)d_in[1];  // [B, NQ, H]
    const float* W_b  = (const float*)d_in[2];  // [H, H]
    const float* W_v  = (const float*)d_in[3];  // [CO, H]
    const float* W_q  = (const float*)d_in[4];  // [CO, H]
    const float* w_hv = (const float*)d_in[5];  // [CO, 1]
    const float* w_hq = (const float*)d_in[6];  // [CO, 1]
    float* out = (float*)d_out;

    float *WqQt, *WvV, *Pv, *Rv, *Mv, *Pq, *Rq, *Mq, *logv, *logq, *part;
    cudaGetSymbolAddress((void**)&WqQt, g_WqQt);
    cudaGetSymbolAddress((void**)&WvV,  g_WvV);
    cudaGetSymbolAddress((void**)&Pv,   g_Pv);
    cudaGetSymbolAddress((void**)&Rv,   g_Rv);
    cudaGetSymbolAddress((void**)&Mv,   g_Mv);
    cudaGetSymbolAddress((void**)&Pq,   g_Pq);
    cudaGetSymbolAddress((void**)&Rq,   g_Rq);
    cudaGetSymbolAddress((void**)&Mq,   g_Mq);
    cudaGetSymbolAddress((void**)&logv, g_logv);
    cudaGetSymbolAddress((void**)&logq, g_logq);
    cudaGetSymbolAddress((void**)&part, g_part);

    const size_t sQ  = (size_t)NQ_ * H_;   // per-batch Q stride
    const size_t sV  = (size_t)H_ * NV_;   // per-batch V stride
    const size_t sCN = (size_t)CO_ * NV_;  // [CO, 2048] stride
    const size_t sCH = (size_t)CO_ * H_;   // [CO, 1024] stride

    // 1. WqQt[b] = W_q @ Q[b]^T         [CO, NQ], K=H
    sgemm128<true ><<<dim3(NQ_/128, CO_/128, B_), 256>>>(W_q, H_, 0, Q, H_, sQ, WqQt, NQ_, sCN, H_);
    // 2. WvV[b] = W_v @ V[b]            [CO, NV], K=H
    sgemm128<false><<<dim3(NV_/128, CO_/128, B_), 256>>>(W_v, H_, 0, V, NV_, sV, WvV, NV_, sCN, H_);
    // 3. Pv[b] = WqQt[b] @ Q[b]         [CO, H], K=NQ
    sgemm128<false><<<dim3(H_/128, CO_/128, B_), 256>>>(WqQt, NQ_, sCN, Q, H_, sQ, Pv, H_, sCH, NQ_);
    // 4. Rv[b] = Pv[b] @ W_b            [CO, H], K=H
    sgemm128<false><<<dim3(H_/128, CO_/128, B_), 256>>>(Pv, H_, sCH, W_b, H_, 0, Rv, H_, sCH, H_);
    // 5. Mv[b] = Rv[b] @ V[b]           [CO, NV], K=H
    sgemm128<false><<<dim3(NV_/128, CO_/128, B_), 256>>>(Rv, H_, sCH, V, NV_, sV, Mv, NV_, sCN, H_);
    // 6. Pq[b] = WvV[b] @ V[b]^T        [CO, H], K=NV
    sgemm128<true ><<<dim3(H_/128, CO_/128, B_), 256>>>(WvV, NV_, sCN, V, NV_, sV, Pq, H_, sCH, NV_);
    // 7. Rq[b] = Pq[b] @ W_b^T          [CO, H], K=H
    sgemm128<true ><<<dim3(H_/128, CO_/128, B_), 256>>>(Pq, H_, sCH, W_b, H_, 0, Rq, H_, sCH, H_);
    // 8. Mq[b] = Rq[b] @ Q[b]^T         [CO, NQ], K=H
    sgemm128<true ><<<dim3(NQ_/128, CO_/128, B_), 256>>>(Rq, H_, sCH, Q, H_, sQ, Mq, NQ_, sCN, H_);

    // logits + softmax
    logits_kernel<<<dim3(NV_/256, B_), 256>>>(WvV,  Mv, w_hv, logv, NV_);
    logits_kernel<<<dim3(NQ_/256, B_), 256>>>(WqQt, Mq, w_hq, logq, NQ_);

    float* out_av = out;                                  // [B,1,NV]
    float* out_aq = out + (size_t)B_ * NV_;               // [B,1,NQ]
    float* out_v  = out + (size_t)B_ * (NV_ + NQ_);       // [B,H]
    float* out_q  = out_v + (size_t)B_ * H_;              // [B,H]

    softmax_kernel<<<B_, 256>>>(logv, out_av, NV_);
    softmax_kernel<<<B_, 256>>>(logq, out_aq, NQ_);

    // v = a_v @ V^T (per batch), q = a_q @ Q (per batch)
    av_V_kernel<<<dim3(H_/8, B_), 256>>>(out_av, V, out_v);
    aq_Q_partial<<<dim3(16, B_), 1024>>>(out_aq, Q, part);
    aq_Q_reduce<<<B_, 1024>>>(part, out_q);
}